// round 1
// baseline (speedup 1.0000x reference)
#include <cuda_runtime.h>
#include <cuda_bf16.h>
#include <cstdint>

// Problem shapes (fixed by the dataset)
#define VOCAB 50000
#define DMODEL 256
#define NCELLS (4 * 64 * 64)   // B*R*C = 16384
#define NTOK 32                // tokens summed per cell

// Scratch: projected embedding table p[v] = E[v] . W
__device__ float g_proj[VOCAB];

// Kernel 1: p[v] = dot(E[v, :], W)   — one warp per vocab row.
// Reads E exactly once (51.2 MB) -> HBM-streaming bound.
__global__ void __launch_bounds__(256) proj_kernel(
    const float* __restrict__ E,
    const float* __restrict__ W)
{
    int gwarp = (blockIdx.x * blockDim.x + threadIdx.x) >> 5;
    int lane  = threadIdx.x & 31;
    if (gwarp >= VOCAB) return;

    const float4* __restrict__ e4 = reinterpret_cast<const float4*>(E + (size_t)gwarp * DMODEL);
    const float4* __restrict__ w4 = reinterpret_cast<const float4*>(W);

    float s = 0.0f;
    // 256 floats = 64 float4; 32 lanes x 2 float4 each
    #pragma unroll
    for (int i = 0; i < 2; ++i) {
        float4 a = e4[lane + i * 32];
        float4 b = w4[lane + i * 32];
        s = fmaf(a.x, b.x, s);
        s = fmaf(a.y, b.y, s);
        s = fmaf(a.z, b.z, s);
        s = fmaf(a.w, b.w, s);
    }
    #pragma unroll
    for (int o = 16; o > 0; o >>= 1)
        s += __shfl_xor_sync(0xFFFFFFFFu, s, o);
    if (lane == 0) g_proj[gwarp] = s;
}

// Kernel 2: out[cell] = sum_t p[x[cell, t]] + bias  — one warp per cell.
// x reads are fully coalesced (32 consecutive int32 per warp);
// p gathers hit a 200 KB table (L1/L2 resident).
__global__ void __launch_bounds__(256) gather_kernel(
    const int* __restrict__ x,
    const float* __restrict__ bias,
    float* __restrict__ out)
{
    int gwarp = (blockIdx.x * blockDim.x + threadIdx.x) >> 5;
    int lane  = threadIdx.x & 31;
    if (gwarp >= NCELLS) return;

    int tok = x[gwarp * NTOK + lane];
    float s = g_proj[tok];

    #pragma unroll
    for (int o = 16; o > 0; o >>= 1)
        s += __shfl_xor_sync(0xFFFFFFFFu, s, o);

    if (lane == 0) out[gwarp] = s + bias[0];
}

extern "C" void kernel_launch(void* const* d_in, const int* in_sizes, int n_in,
                              void* d_out, int out_size)
{
    const int*   x = (const int*)  d_in[0];   // [B,R,C,T] int32
    const float* E = (const float*)d_in[1];   // [VOCAB, D] f32
    const float* W = (const float*)d_in[2];   // [D] f32
    const float* b = (const float*)d_in[3];   // [1] f32
    float* out = (float*)d_out;               // [B,R,C] f32

    // Kernel 1: 50000 warps -> 6250 blocks of 256 threads (8 warps)
    proj_kernel<<<(VOCAB * 32 + 255) / 256, 256>>>(E, W);
    // Kernel 2: 16384 warps -> 2048 blocks of 256 threads
    gather_kernel<<<(NCELLS * 32 + 255) / 256, 256>>>(x, b, out);
}

// round 2
// speedup vs baseline: 1.1572x; 1.1572x over previous
#include <cuda_runtime.h>
#include <cuda_bf16.h>
#include <cstdint>

#define VOCAB 50000
#define DMODEL 256
#define NCELLS (4 * 64 * 64)   // 16384
#define NTOK 32

__device__ float g_proj[VOCAB];

// Kernel 1: p[v] = dot(E[v,:], W). One warp handles TWO vocab rows
// -> 4 outstanding LDG.128 per thread (higher MLP for HBM streaming).
__global__ void __launch_bounds__(256) proj_kernel(
    const float* __restrict__ E,
    const float* __restrict__ W)
{
    int gwarp = (blockIdx.x * blockDim.x + threadIdx.x) >> 5;
    int lane  = threadIdx.x & 31;
    int row0  = gwarp * 2;
    if (row0 >= VOCAB) return;

    const float4* __restrict__ e4 = reinterpret_cast<const float4*>(E);
    const float4* __restrict__ w4 = reinterpret_cast<const float4*>(W);

    // W is L1-resident after first block on each SM
    float4 wa = w4[lane];
    float4 wb = w4[lane + 32];

    // Front-batch all 4 row loads (64 float4 per row)
    float4 a0 = e4[(size_t)row0 * 64 + lane];
    float4 a1 = e4[(size_t)row0 * 64 + lane + 32];
    float4 b0 = e4[(size_t)(row0 + 1) * 64 + lane];
    float4 b1 = e4[(size_t)(row0 + 1) * 64 + lane + 32];

    float s0 = 0.f, s1 = 0.f;
    s0 = fmaf(a0.x, wa.x, s0); s0 = fmaf(a0.y, wa.y, s0);
    s0 = fmaf(a0.z, wa.z, s0); s0 = fmaf(a0.w, wa.w, s0);
    s0 = fmaf(a1.x, wb.x, s0); s0 = fmaf(a1.y, wb.y, s0);
    s0 = fmaf(a1.z, wb.z, s0); s0 = fmaf(a1.w, wb.w, s0);
    s1 = fmaf(b0.x, wa.x, s1); s1 = fmaf(b0.y, wa.y, s1);
    s1 = fmaf(b0.z, wa.z, s1); s1 = fmaf(b0.w, wa.w, s1);
    s1 = fmaf(b1.x, wb.x, s1); s1 = fmaf(b1.y, wb.y, s1);
    s1 = fmaf(b1.z, wb.z, s1); s1 = fmaf(b1.w, wb.w, s1);

    #pragma unroll
    for (int o = 16; o > 0; o >>= 1) {
        s0 += __shfl_xor_sync(0xFFFFFFFFu, s0, o);
        s1 += __shfl_xor_sync(0xFFFFFFFFu, s1, o);
    }
    if (lane == 0) {
        g_proj[row0]     = s0;
        g_proj[row0 + 1] = s1;
    }
}

// Kernel 2: out[cell] = sum_t p[x[cell,t]] + bias.
// 8 threads per cell: each lane loads int4 (4 tokens, coalesced 512B/warp),
// 4 independent gathers (MLP=4), 3-step shuffle reduce over 8 lanes.
__global__ void __launch_bounds__(256) gather_kernel(
    const int* __restrict__ x,
    const float* __restrict__ bias,
    float* __restrict__ out)
{
    int tid  = blockIdx.x * blockDim.x + threadIdx.x;
    int lane = threadIdx.x & 31;
    int warp = tid >> 5;
    int cell = warp * 4 + (lane >> 3);
    int sub  = lane & 7;
    if (cell >= NCELLS) return;

    int4 t = reinterpret_cast<const int4*>(x)[cell * 8 + sub];

    float s = g_proj[t.x] + g_proj[t.y] + g_proj[t.z] + g_proj[t.w];

    s += __shfl_xor_sync(0xFFFFFFFFu, s, 4);
    s += __shfl_xor_sync(0xFFFFFFFFu, s, 2);
    s += __shfl_xor_sync(0xFFFFFFFFu, s, 1);

    if (sub == 0) out[cell] = s + bias[0];
}

extern "C" void kernel_launch(void* const* d_in, const int* in_sizes, int n_in,
                              void* d_out, int out_size)
{
    const int*   x = (const int*)  d_in[0];
    const float* E = (const float*)d_in[1];
    const float* W = (const float*)d_in[2];
    const float* b = (const float*)d_in[3];
    float* out = (float*)d_out;

    // proj: 25000 warps (2 rows each) -> 3125 blocks of 256
    proj_kernel<<<(VOCAB / 2 * 32 + 255) / 256, 256>>>(E, W);
    // gather: 4096 warps (4 cells each) -> 512 blocks of 256
    gather_kernel<<<(NCELLS / 4 * 32 + 255) / 256, 256>>>(x, b, out);
}